// round 1
// baseline (speedup 1.0000x reference)
#include <cuda_runtime.h>
#include <cuda_bf16.h>

// NMS: B=32 batches, N=2048 boxes, keep first R=100 surviving boxes.
// pred layout: [B, N, 5] = (score, left, top, right, bottom)
// out layout:  [B, R, 3] = (top, right, bottom) of kept boxes (sorted by score), zero-padded.

#define NMS_N 2048
#define NMS_R 100
#define NMS_THREADS 1024

__device__ __forceinline__ unsigned int float_to_ordered(float f) {
    unsigned int u = __float_as_uint(f);
    // monotone-increasing unsigned mapping
    return (u & 0x80000000u) ? ~u : (u | 0x80000000u);
}

__global__ __launch_bounds__(NMS_THREADS, 1)
void nms_kernel(const float* __restrict__ pred, float* __restrict__ out) {
    __shared__ unsigned long long keys[NMS_N];     // 16 KB
    __shared__ float4 keptBox[NMS_R];              // (l, t, r, b) of kept boxes
    __shared__ float  keptVals[NMS_R * 3];         // (t, r, b) output values
    __shared__ int    sh_nkept;

    const int b   = blockIdx.x;
    const int tid = threadIdx.x;
    const float* batch = pred + (size_t)b * NMS_N * 5;

    // ---- Phase 1: build sort keys: descending score, ties by ascending index ----
    {
        int i0 = tid;           // 1024 threads, 2048 elements -> 2 per thread
        int i1 = tid + NMS_THREADS;
        float s0 = batch[i0 * 5 + 0];
        float s1 = batch[i1 * 5 + 0];
        keys[i0] = ((unsigned long long)(~float_to_ordered(s0)) << 32) | (unsigned int)i0;
        keys[i1] = ((unsigned long long)(~float_to_ordered(s1)) << 32) | (unsigned int)i1;
    }
    __syncthreads();

    // ---- Phase 2: bitonic sort ascending (=> scores descending) ----
    for (unsigned int k = 2; k <= NMS_N; k <<= 1) {
        for (unsigned int j = k >> 1; j > 0; j >>= 1) {
            unsigned int i  = tid;                                   // one pair per thread
            unsigned int lo = ((i & ~(j - 1u)) << 1) | (i & (j - 1u));
            unsigned int hi = lo | j;
            unsigned long long a = keys[lo];
            unsigned long long c = keys[hi];
            bool ascend = ((lo & k) == 0u);
            if ((a > c) == ascend) { keys[lo] = c; keys[hi] = a; }
            __syncthreads();
        }
    }

    // ---- Phase 3: greedy NMS by warp 0, early-terminate at R kept ----
    if (tid < 32) {
        const int lane = tid;
        int nkept = 0;
        for (int c = 0; c < NMS_N && nkept < NMS_R; ++c) {
            unsigned int idx = (unsigned int)(keys[c] & 0xFFFFFFFFu);
            const float* pp = batch + (size_t)idx * 5;
            float l  = pp[1];
            float t  = pp[2];
            float r  = pp[3];
            float bt = pp[4];
            float area = (r - l) * (bt - t);

            bool sup = false;
            for (int kk = lane; kk < nkept; kk += 32) {
                float4 kb = keptBox[kk];
                float il = fmaxf(kb.x, l);
                float it = fmaxf(kb.y, t);
                float ir = fminf(kb.z, r);
                float ib = fminf(kb.w, bt);
                float inter = fmaxf(0.0f, ir - il) * fmaxf(0.0f, ib - it);
                if (inter / area >= 0.5f) sup = true;
            }
            if (!__any_sync(0xFFFFFFFFu, sup)) {
                if (lane == 0) {
                    keptBox[nkept] = make_float4(l, t, r, bt);
                    keptVals[nkept * 3 + 0] = t;
                    keptVals[nkept * 3 + 1] = r;
                    keptVals[nkept * 3 + 2] = bt;
                }
                nkept++;
                __syncwarp();
            }
        }
        if (lane == 0) sh_nkept = nkept;
    }
    __syncthreads();

    // ---- Phase 4: write output [R, 3], zero-padded ----
    int nk = sh_nkept;
    for (int o = tid; o < NMS_R * 3; o += NMS_THREADS) {
        int slot = o / 3;
        out[(size_t)b * NMS_R * 3 + o] = (slot < nk) ? keptVals[o] : 0.0f;
    }
}

extern "C" void kernel_launch(void* const* d_in, const int* in_sizes, int n_in,
                              void* d_out, int out_size) {
    const float* pred = (const float*)d_in[0];
    float* out = (float*)d_out;
    nms_kernel<<<32, NMS_THREADS>>>(pred, out);
}

// round 2
// speedup vs baseline: 2.2845x; 2.2845x over previous
#include <cuda_runtime.h>
#include <cuda_bf16.h>

// NMS: B=32 batches, N=2048 boxes, keep first R=100 surviving boxes.
// pred layout: [B, N, 5] = (score, left, top, right, bottom)
// out layout:  [B, R, 3] = (top, right, bottom) of kept boxes (score-desc order), zero-padded.

#define NMS_N 2048
#define NMS_R 100
#define NMS_THREADS 1024   // 32 warps; warp w owns elements [64w, 64w+64)

typedef unsigned long long ull;

__device__ __forceinline__ unsigned int float_to_ordered(float f) {
    unsigned int u = __float_as_uint(f);
    return (u & 0x80000000u) ? ~u : (u | 0x80000000u);
}

__device__ __forceinline__ ull umin64(ull a, ull b) { return a < b ? a : b; }
__device__ __forceinline__ ull umax64(ull a, ull b) { return a > b ? a : b; }

__global__ __launch_bounds__(NMS_THREADS, 1)
void nms_kernel(const float* __restrict__ pred, float* __restrict__ out) {
    __shared__ ull   keys[NMS_N];          // 16 KB
    __shared__ float keptVals[NMS_R * 3];  // (t, r, b) output values
    __shared__ int   sh_nkept;

    const int b    = blockIdx.x;
    const int tid  = threadIdx.x;
    const int w    = tid >> 5;
    const int lane = tid & 31;
    const float* batch = pred + (size_t)b * NMS_N * 5;

    // Element indices owned by this lane (register-resident pair for bitonic)
    const int xa = (w << 6) | lane;      // [64w + lane]
    const int xb = xa + 32;              // [64w + 32 + lane]

    // ---- Phase 1: build keys in registers: desc score, ties asc index ----
    ull a, c;
    {
        float sa = __ldg(batch + (size_t)xa * 5);
        float sb = __ldg(batch + (size_t)xb * 5);
        a = ((ull)(~float_to_ordered(sa)) << 32) | (unsigned int)xa;
        c = ((ull)(~float_to_ordered(sb)) << 32) | (unsigned int)xb;
    }

    // ---- Phase 2: hybrid bitonic sort (ascending u64 == descending score) ----
    // Register pass for (k, j<=32): j==32 is an in-thread a<->c swap; j<=16 via shfl_xor.
    #define REG_PASS(k, j) do {                                                   \
        if ((j) == 32) {                                                          \
            bool dir = ((xa & (k)) == 0);                                         \
            if ((a > c) == dir) { ull t_ = a; a = c; c = t_; }                    \
        } else {                                                                  \
            ull pa = __shfl_xor_sync(0xFFFFFFFFu, a, (j));                        \
            ull pc = __shfl_xor_sync(0xFFFFFFFFu, c, (j));                        \
            bool low = ((lane & (j)) == 0);                                       \
            bool da  = ((xa & (k)) == 0);                                         \
            bool dc  = ((xb & (k)) == 0);                                         \
            a = (low == da) ? umin64(a, pa) : umax64(a, pa);                      \
            c = (low == dc) ? umin64(c, pc) : umax64(c, pc);                      \
        }                                                                         \
    } while (0)

    // Stages k=2..64: fully in registers, zero barriers
    #pragma unroll
    for (int k = 2; k <= 64; k <<= 1) {
        #pragma unroll
        for (int j = (k > 32 ? 32 : (k >> 1)); j >= 1; j >>= 1) {
            REG_PASS(k, j);
        }
    }

    // Stages k=128..2048: j>=64 in shared (coalesced, conflict-free), j<=32 in registers
    #pragma unroll
    for (int k = 128; k <= NMS_N; k <<= 1) {
        keys[xa] = a; keys[xb] = c;
        __syncthreads();
        for (int j = (k >> 1); j >= 64; j >>= 1) {
            unsigned int lo = ((tid & ~(j - 1)) << 1) | (tid & (j - 1));
            unsigned int hi = lo | j;
            ull u = keys[lo];
            ull v = keys[hi];
            bool dir = ((lo & k) == 0);
            if ((u > v) == dir) { keys[lo] = v; keys[hi] = u; }
            __syncthreads();
        }
        a = keys[xa]; c = keys[xb];
        #pragma unroll
        for (int j = 32; j >= 1; j >>= 1) {
            REG_PASS(k, j);
        }
    }

    // Final: sorted keys to shared for the greedy scan
    keys[xa] = a; keys[xb] = c;
    __syncthreads();

    // ---- Phase 3: greedy NMS by warp 0; kept boxes live in registers ----
    if (w == 0) {
        float4 kept0, kept1, kept2, kept3;  // lane L holds kept slots L, L+32, L+64, L+96
        int nkept = 0;

        // prefetch candidate 0
        int   idx_n = (int)(keys[0] & 0x7FF);
        const float* pn = batch + (size_t)idx_n * 5;
        float l_n = __ldg(pn + 1), t_n = __ldg(pn + 2), r_n = __ldg(pn + 3), b_n = __ldg(pn + 4);

        for (int cd = 0; cd < NMS_N && nkept < NMS_R; ++cd) {
            float bl = l_n, btp = t_n, br = r_n, bb = b_n;
            // prefetch next candidate (independent of this iteration's outcome)
            if (cd + 1 < NMS_N) {
                idx_n = (int)(keys[cd + 1] & 0x7FF);
                const float* p2 = batch + (size_t)idx_n * 5;
                l_n = __ldg(p2 + 1); t_n = __ldg(p2 + 2); r_n = __ldg(p2 + 3); b_n = __ldg(p2 + 4);
            }

            float half_area = 0.5f * (br - bl) * (bb - btp);

            bool sup = false;
            #pragma unroll
            for (int s = 0; s < 4; ++s) {
                int kk = (s << 5) + lane;
                if (kk < nkept) {
                    float4 kb = (s == 0) ? kept0 : (s == 1) ? kept1 : (s == 2) ? kept2 : kept3;
                    float il = fmaxf(kb.x, bl);
                    float it = fmaxf(kb.y, btp);
                    float ir = fminf(kb.z, br);
                    float ib = fminf(kb.w, bb);
                    float inter = fmaxf(0.0f, ir - il) * fmaxf(0.0f, ib - it);
                    sup |= (inter >= half_area);
                }
            }
            if (!__any_sync(0xFFFFFFFFu, sup)) {
                int slot = nkept >> 5;
                if ((nkept & 31) == lane) {
                    float4 nb = make_float4(bl, btp, br, bb);
                    if      (slot == 0) kept0 = nb;
                    else if (slot == 1) kept1 = nb;
                    else if (slot == 2) kept2 = nb;
                    else                kept3 = nb;
                }
                if (lane == 0) {
                    keptVals[nkept * 3 + 0] = btp;
                    keptVals[nkept * 3 + 1] = br;
                    keptVals[nkept * 3 + 2] = bb;
                }
                nkept++;
            }
        }
        if (lane == 0) sh_nkept = nkept;
    }
    __syncthreads();

    // ---- Phase 4: write output [R, 3], zero-padded ----
    int nk = sh_nkept;
    if (tid < NMS_R * 3) {
        int slot = tid / 3;
        out[(size_t)b * NMS_R * 3 + tid] = (slot < nk) ? keptVals[tid] : 0.0f;
    }
}

extern "C" void kernel_launch(void* const* d_in, const int* in_sizes, int n_in,
                              void* d_out, int out_size) {
    const float* pred = (const float*)d_in[0];
    float* out = (float*)d_out;
    nms_kernel<<<32, NMS_THREADS>>>(pred, out);
}

// round 3
// speedup vs baseline: 2.6189x; 1.1464x over previous
#include <cuda_runtime.h>
#include <cuda_bf16.h>

// NMS: B=32, N=2048, keep first R=100 surviving boxes (greedy, score-desc).
// pred: [B, N, 5] = (score, l, t, r, b);  out: [B, R, 3] = (t, r, b), zero-padded.
//
// Fast path: histogram-select top ~320 scores exactly (bucket threshold),
// sort only those 512 slots, greedy scan vs register-resident kept list.
// Fallback (deterministic, ~never taken): full 2048 bitonic + greedy.

#define NMS_N   2048
#define NMS_R   100
#define NT      256
#define EPT     8          // elements per thread (NT*EPT == NMS_N)
#define TARGET  320
#define SEL_CAP 512

typedef unsigned long long ull;

__device__ __forceinline__ unsigned int float_to_ordered(float f) {
    unsigned int u = __float_as_uint(f);
    return (u & 0x80000000u) ? ~u : (u | 0x80000000u);
}
__device__ __forceinline__ ull umin64(ull a, ull b) { return a < b ? a : b; }
__device__ __forceinline__ ull umax64(ull a, ull b) { return a > b ? a : b; }

__global__ __launch_bounds__(NT, 1)
void nms_kernel(const float* __restrict__ pred, float* __restrict__ out) {
    // 16KB pool, aliased:
    //   fast path: selBoxes[512] (8KB) | selKeys[512] (4KB) | selHalf[512] (2KB) | hist[512] (2KB)
    //   fallback : fullKeys[2048] (16KB)
    __shared__ __align__(16) ull pool[2048];
    float4*       selBoxes = (float4*)pool;               // [SEL_CAP]
    ull*          selKeys  = pool + 1024;                 // [SEL_CAP]
    float*        selHalf  = (float*)(pool + 1536);       // [SEL_CAP]
    unsigned int* hist     = (unsigned int*)(pool + 1792);// [512]
    ull*          fullKeys = pool;                        // [NMS_N] (fallback)

    __shared__ float keptVals[NMS_R * 3];
    __shared__ int   selCount, thrB, fbFlag, sh_nkept;

    const int b    = blockIdx.x;
    const int tid  = threadIdx.x;
    const int lane = tid & 31;
    const int w    = tid >> 5;
    const float* batch = pred + (size_t)b * NMS_N * 5;

    hist[tid] = 0; hist[tid + 256] = 0;
    if (tid == 0) { selCount = 0; fbFlag = 0; }
    __syncthreads();

    // ---- Phase 1: load scores, histogram (512 buckets over [0,1)) ----
    float sc[EPT];
    int   bk[EPT];
    #pragma unroll
    for (int p = 0; p < EPT; p++) {
        int e = tid + p * NT;
        float s = __ldg(batch + (size_t)e * 5);
        sc[p] = s;
        int bb = (int)(s * 512.0f);
        bb = bb < 0 ? 0 : (bb > 511 ? 511 : bb);
        bk[p] = bb;
        atomicAdd(&hist[bb], 1u);
    }
    __syncthreads();

    // ---- Phase 2: find threshold bucket B (suffix count >= TARGET), warp 0 ----
    if (w == 0) {
        int base = 512 - 16 * (lane + 1);   // lane 0 covers the top 16 buckets
        unsigned partial = 0;
        #pragma unroll
        for (int i = 0; i < 16; i++) partial += hist[base + i];
        unsigned cum = partial;             // inclusive scan, lane order = top-down
        #pragma unroll
        for (int d = 1; d < 32; d <<= 1) {
            unsigned v = __shfl_up_sync(0xFFFFFFFFu, cum, d);
            if (lane >= d) cum += v;
        }
        unsigned mask = __ballot_sync(0xFFFFFFFFu, cum >= TARGET);
        int fl = __ffs(mask) - 1;
        if (lane == fl) {
            unsigned run = cum - partial;
            int bsel = base;
            for (int bb = base + 15; bb >= base; bb--) {
                run += hist[bb];
                if (run >= TARGET) { bsel = bb; break; }
            }
            thrB = bsel;
        }
    }
    __syncthreads();
    const int B0 = thrB;

    // ---- Phase 3: compact selected elements; gather boxes into shared ----
    #pragma unroll
    for (int p = 0; p < EPT; p++) {
        if (bk[p] >= B0) {
            int pos = atomicAdd(&selCount, 1);
            if (pos < SEL_CAP) {
                int e = tid + p * NT;
                const float* pp = batch + (size_t)e * 5;
                float l = __ldg(pp + 1), t = __ldg(pp + 2);
                float r = __ldg(pp + 3), bo = __ldg(pp + 4);
                selBoxes[pos] = make_float4(l, t, r, bo);
                selHalf[pos]  = 0.5f * (r - l) * (bo - t);
                // key: (desc-ordered score | origIdx | slot). slot bits never
                // affect order (origIdx unique) -> deterministic output.
                selKeys[pos] = ((ull)(~float_to_ordered(sc[p])) << 21)
                             | ((ull)e << 10) | (unsigned)pos;
            }
        }
    }
    __syncthreads();
    const int nsel = selCount;
    if (nsel > SEL_CAP && tid == 0) fbFlag = 1;
    __syncthreads();

    #define REG_PASS(k, j) do {                                                 \
        if ((j) == 32) {                                                        \
            bool dir = ((xa & (k)) == 0);                                       \
            if ((a > c) == dir) { ull t_ = a; a = c; c = t_; }                  \
        } else {                                                                \
            ull pa = __shfl_xor_sync(0xFFFFFFFFu, a, (j));                      \
            ull pc = __shfl_xor_sync(0xFFFFFFFFu, c, (j));                      \
            bool low = ((lane & (j)) == 0);                                     \
            bool da  = ((xa & (k)) == 0);                                       \
            bool dc  = ((xb & (k)) == 0);                                       \
            a = (low == da) ? umin64(a, pa) : umax64(a, pa);                    \
            c = (low == dc) ? umin64(c, pc) : umax64(c, pc);                    \
        }                                                                       \
    } while (0)

    if (!fbFlag) {
        // pad: max keys sort last; slot bits forced 0 so prefetch reads stay in-bounds
        for (int i = nsel + tid; i < SEL_CAP; i += NT) selKeys[i] = ~(ull)0x3FF;
        __syncthreads();

        // ---- Phase 4: hybrid bitonic sort of 512 keys (8 warps, 2 regs/thread) ----
        const int xa = (w << 6) | lane;
        const int xb = xa + 32;
        ull a = selKeys[xa], c = selKeys[xb];

        #pragma unroll
        for (int k = 2; k <= 64; k <<= 1) {
            #pragma unroll
            for (int j = (k > 32 ? 32 : (k >> 1)); j >= 1; j >>= 1) REG_PASS(k, j);
        }
        #pragma unroll
        for (int k = 128; k <= SEL_CAP; k <<= 1) {
            selKeys[xa] = a; selKeys[xb] = c;
            __syncthreads();
            for (int j = (k >> 1); j >= 64; j >>= 1) {
                unsigned int i  = tid;
                unsigned int lo = ((i & ~(j - 1)) << 1) | (i & (j - 1));
                unsigned int hi = lo | j;
                ull u = selKeys[lo], v = selKeys[hi];
                bool dir = ((lo & k) == 0);
                if ((u > v) == dir) { selKeys[lo] = v; selKeys[hi] = u; }
                __syncthreads();
            }
            a = selKeys[xa]; c = selKeys[xb];
            #pragma unroll
            for (int j = 32; j >= 1; j >>= 1) REG_PASS(k, j);
        }
        selKeys[xa] = a; selKeys[xb] = c;
        __syncthreads();

        // ---- Phase 5: greedy scan (warp 0), kept boxes in registers ----
        if (w == 0) {
            float4 kept0, kept1, kept2, kept3;
            int nkept = 0;
            ull key0 = selKeys[0];
            int s0 = (int)(key0 & 0x3FF);
            float4 bx = selBoxes[s0];
            float  ha = selHalf[s0];
            for (int cd = 0; cd < nsel && nkept < NMS_R; ++cd) {
                float4 cb = bx; float hh = ha;
                if (cd + 1 < nsel) {
                    ull kn = selKeys[cd + 1];
                    int sn = (int)(kn & 0x3FF);
                    bx = selBoxes[sn]; ha = selHalf[sn];
                }
                bool sup = false;
                #pragma unroll
                for (int s = 0; s < 4; ++s) {
                    int kk = (s << 5) + lane;
                    if (kk < nkept) {
                        float4 kb = (s == 0) ? kept0 : (s == 1) ? kept1 : (s == 2) ? kept2 : kept3;
                        float il = fmaxf(kb.x, cb.x);
                        float it = fmaxf(kb.y, cb.y);
                        float ir = fminf(kb.z, cb.z);
                        float ib = fminf(kb.w, cb.w);
                        float inter = fmaxf(0.0f, ir - il) * fmaxf(0.0f, ib - it);
                        sup |= (inter >= hh);
                    }
                }
                if (!__any_sync(0xFFFFFFFFu, sup)) {
                    int slot = nkept >> 5;
                    if ((nkept & 31) == lane) {
                        if      (slot == 0) kept0 = cb;
                        else if (slot == 1) kept1 = cb;
                        else if (slot == 2) kept2 = cb;
                        else                kept3 = cb;
                    }
                    if (lane == 0) {
                        keptVals[nkept * 3 + 0] = cb.y;
                        keptVals[nkept * 3 + 1] = cb.z;
                        keptVals[nkept * 3 + 2] = cb.w;
                    }
                    nkept++;
                }
            }
            if (lane == 0) sh_nkept = nkept;
        }
        __syncthreads();
        if (tid == 0 && sh_nkept < NMS_R) fbFlag = 1;   // selection too shallow
        __syncthreads();
    }

    // ---- Fallback: full 2048 sort + greedy from global (exact, rarely taken) ----
    if (fbFlag) {
        #pragma unroll
        for (int p = 0; p < EPT; p++) {
            int e = tid + p * NT;
            fullKeys[e] = ((ull)(~float_to_ordered(sc[p])) << 32) | (unsigned)e;
        }
        __syncthreads();
        for (unsigned int k = 2; k <= NMS_N; k <<= 1) {
            for (unsigned int j = k >> 1; j > 0; j >>= 1) {
                #pragma unroll
                for (int p = 0; p < 4; p++) {
                    unsigned int i  = tid + p * NT;          // 1024 pairs
                    unsigned int lo = ((i & ~(j - 1)) << 1) | (i & (j - 1));
                    unsigned int hi = lo | j;
                    ull u = fullKeys[lo], v = fullKeys[hi];
                    bool dir = ((lo & k) == 0);
                    if ((u > v) == dir) { fullKeys[lo] = v; fullKeys[hi] = u; }
                }
                __syncthreads();
            }
        }
        if (w == 0) {
            float4 kept0, kept1, kept2, kept3;
            int nkept = 0;
            int idx_n = (int)(fullKeys[0] & 0x7FF);
            const float* pn = batch + (size_t)idx_n * 5;
            float l_n = __ldg(pn + 1), t_n = __ldg(pn + 2), r_n = __ldg(pn + 3), b_n = __ldg(pn + 4);
            for (int cd = 0; cd < NMS_N && nkept < NMS_R; ++cd) {
                float bl = l_n, btp = t_n, br = r_n, bb2 = b_n;
                if (cd + 1 < NMS_N) {
                    idx_n = (int)(fullKeys[cd + 1] & 0x7FF);
                    const float* p2 = batch + (size_t)idx_n * 5;
                    l_n = __ldg(p2 + 1); t_n = __ldg(p2 + 2); r_n = __ldg(p2 + 3); b_n = __ldg(p2 + 4);
                }
                float half_area = 0.5f * (br - bl) * (bb2 - btp);
                bool sup = false;
                #pragma unroll
                for (int s = 0; s < 4; ++s) {
                    int kk = (s << 5) + lane;
                    if (kk < nkept) {
                        float4 kb = (s == 0) ? kept0 : (s == 1) ? kept1 : (s == 2) ? kept2 : kept3;
                        float il = fmaxf(kb.x, bl);
                        float it = fmaxf(kb.y, btp);
                        float ir = fminf(kb.z, br);
                        float ib = fminf(kb.w, bb2);
                        float inter = fmaxf(0.0f, ir - il) * fmaxf(0.0f, ib - it);
                        sup |= (inter >= half_area);
                    }
                }
                if (!__any_sync(0xFFFFFFFFu, sup)) {
                    int slot = nkept >> 5;
                    if ((nkept & 31) == lane) {
                        float4 nb = make_float4(bl, btp, br, bb2);
                        if      (slot == 0) kept0 = nb;
                        else if (slot == 1) kept1 = nb;
                        else if (slot == 2) kept2 = nb;
                        else                kept3 = nb;
                    }
                    if (lane == 0) {
                        keptVals[nkept * 3 + 0] = btp;
                        keptVals[nkept * 3 + 1] = br;
                        keptVals[nkept * 3 + 2] = bb2;
                    }
                    nkept++;
                }
            }
            if (lane == 0) sh_nkept = nkept;
        }
        __syncthreads();
    }

    // ---- Output: [R,3], zero-padded ----
    int nk = sh_nkept;
    for (int o = tid; o < NMS_R * 3; o += NT) {
        int slot = o / 3;
        out[(size_t)b * NMS_R * 3 + o] = (slot < nk) ? keptVals[o] : 0.0f;
    }
}

extern "C" void kernel_launch(void* const* d_in, const int* in_sizes, int n_in,
                              void* d_out, int out_size) {
    const float* pred = (const float*)d_in[0];
    float* out = (float*)d_out;
    nms_kernel<<<32, NT>>>(pred, out);
}

// round 4
// speedup vs baseline: 5.3653x; 2.0487x over previous
#include <cuda_runtime.h>
#include <cuda_bf16.h>

// NMS: B=32, N=2048, keep first R=100 surviving boxes (greedy, score-desc).
// pred: [B, N, 5] = (score, l, t, r, b);  out: [B, R, 3] = (t, r, b), zero-padded.

#define NMS_N   2048
#define NMS_R   100
#define NT      256
#define EPT     8
#define TARGET  320
#define SEL_CAP 512

typedef unsigned long long ull;

__device__ __forceinline__ unsigned int float_to_ordered(float f) {
    unsigned int u = __float_as_uint(f);
    return (u & 0x80000000u) ? ~u : (u | 0x80000000u);
}
__device__ __forceinline__ ull umin64(ull a, ull b) { return a < b ? a : b; }
__device__ __forceinline__ ull umax64(ull a, ull b) { return a > b ? a : b; }

// suppression test: inter(kb, cb) >= hh (= 0.5 * area(cb)); sentinel kb yields false
__device__ __forceinline__ bool iou_sup(const float4 kb, const float4 cb, float hh) {
    float il = fmaxf(kb.x, cb.x);
    float it = fmaxf(kb.y, cb.y);
    float ir = fminf(kb.z, cb.z);
    float ib = fminf(kb.w, cb.w);
    return fmaxf(0.0f, ir - il) * fmaxf(0.0f, ib - it) >= hh;
}
__device__ __forceinline__ void selset(float4& d, const float4 s, bool p) {
    d.x = p ? s.x : d.x; d.y = p ? s.y : d.y;
    d.z = p ? s.z : d.z; d.w = p ? s.w : d.w;
}

__global__ __launch_bounds__(NT, 1)
void nms_kernel(const float* __restrict__ pred, float* __restrict__ out) {
    // pool (16KB): fast path = selBoxes[512] | selKeys[512] | selHalf[512] | hist[512]
    //              fallback  = fullKeys[2048]
    __shared__ __align__(16) ull pool[2048];
    float4*       selBoxes = (float4*)pool;
    ull*          selKeys  = pool + 1024;
    float*        selHalf  = (float*)(pool + 1536);
    unsigned int* hist     = (unsigned int*)(pool + 1792);
    ull*          fullKeys = pool;

    __shared__ __align__(16) float4 sortedBoxes[SEL_CAP];  // 8KB
    __shared__ float sortedHalf[SEL_CAP];                  // 2KB
    __shared__ float keptVals[NMS_R * 3];
    __shared__ int   selCount, thrB, fbFlag, sh_nkept;

    const int b    = blockIdx.x;
    const int tid  = threadIdx.x;
    const int lane = tid & 31;
    const int w    = tid >> 5;
    const float* batch = pred + (size_t)b * NMS_N * 5;

    hist[tid] = 0; hist[tid + 256] = 0;
    if (tid == 0) { selCount = 0; fbFlag = 0; }
    __syncthreads();

    // ---- Phase 1: scores + histogram (512 buckets over [0,1)) ----
    float sc[EPT];
    int   bk[EPT];
    #pragma unroll
    for (int p = 0; p < EPT; p++) {
        int e = tid + p * NT;
        float s = __ldg(batch + (size_t)e * 5);
        sc[p] = s;
        int bb = (int)(s * 512.0f);
        bb = bb < 0 ? 0 : (bb > 511 ? 511 : bb);
        bk[p] = bb;
        atomicAdd(&hist[bb], 1u);
    }
    __syncthreads();

    // ---- Phase 2: threshold bucket (suffix count >= TARGET), warp 0 ----
    if (w == 0) {
        int base = 512 - 16 * (lane + 1);
        unsigned partial = 0;
        #pragma unroll
        for (int i = 0; i < 16; i++) partial += hist[base + i];
        unsigned cum = partial;
        #pragma unroll
        for (int d = 1; d < 32; d <<= 1) {
            unsigned v = __shfl_up_sync(0xFFFFFFFFu, cum, d);
            if (lane >= d) cum += v;
        }
        unsigned mask = __ballot_sync(0xFFFFFFFFu, cum >= TARGET);
        int fl = __ffs(mask) - 1;
        if (lane == fl) {
            unsigned run = cum - partial;
            int bsel = base;
            for (int bb = base + 15; bb >= base; bb--) {
                run += hist[bb];
                if (run >= TARGET) { bsel = bb; break; }
            }
            thrB = bsel;
        }
    }
    __syncthreads();
    const int B0q = thrB;

    // ---- Phase 3: compact selected; gather boxes ----
    #pragma unroll
    for (int p = 0; p < EPT; p++) {
        if (bk[p] >= B0q) {
            int pos = atomicAdd(&selCount, 1);
            if (pos < SEL_CAP) {
                int e = tid + p * NT;
                const float* pp = batch + (size_t)e * 5;
                float l = __ldg(pp + 1), t = __ldg(pp + 2);
                float r = __ldg(pp + 3), bo = __ldg(pp + 4);
                selBoxes[pos] = make_float4(l, t, r, bo);
                selHalf[pos]  = 0.5f * (r - l) * (bo - t);
                selKeys[pos] = ((ull)(~float_to_ordered(sc[p])) << 21)
                             | ((ull)e << 10) | (unsigned)pos;
            }
        }
    }
    __syncthreads();
    const int nsel = selCount;
    if (nsel > SEL_CAP && tid == 0) fbFlag = 1;
    __syncthreads();

    #define REG_PASS(k, j) do {                                                 \
        if ((j) == 32) {                                                        \
            bool dir = ((xa & (k)) == 0);                                       \
            if ((a > c) == dir) { ull t_ = a; a = c; c = t_; }                  \
        } else {                                                                \
            ull pa = __shfl_xor_sync(0xFFFFFFFFu, a, (j));                      \
            ull pc = __shfl_xor_sync(0xFFFFFFFFu, c, (j));                      \
            bool low = ((lane & (j)) == 0);                                     \
            bool da  = ((xa & (k)) == 0);                                       \
            bool dc  = ((xb & (k)) == 0);                                       \
            a = (low == da) ? umin64(a, pa) : umax64(a, pa);                    \
            c = (low == dc) ? umin64(c, pc) : umax64(c, pc);                    \
        }                                                                       \
    } while (0)

    if (!fbFlag) {
        for (int i = nsel + tid; i < SEL_CAP; i += NT) selKeys[i] = ~(ull)0x3FF;
        __syncthreads();

        // ---- Phase 4: hybrid bitonic sort of 512 keys ----
        const int xa = (w << 6) | lane;
        const int xb = xa + 32;
        ull a = selKeys[xa], c = selKeys[xb];
        #pragma unroll
        for (int k = 2; k <= 64; k <<= 1) {
            #pragma unroll
            for (int j = (k > 32 ? 32 : (k >> 1)); j >= 1; j >>= 1) REG_PASS(k, j);
        }
        #pragma unroll
        for (int k = 128; k <= SEL_CAP; k <<= 1) {
            selKeys[xa] = a; selKeys[xb] = c;
            __syncthreads();
            for (int j = (k >> 1); j >= 64; j >>= 1) {
                unsigned int i  = tid;
                unsigned int lo = ((i & ~(j - 1)) << 1) | (i & (j - 1));
                unsigned int hi = lo | j;
                ull u = selKeys[lo], v = selKeys[hi];
                bool dir = ((lo & k) == 0);
                if ((u > v) == dir) { selKeys[lo] = v; selKeys[hi] = u; }
                __syncthreads();
            }
            a = selKeys[xa]; c = selKeys[xb];
            #pragma unroll
            for (int j = 32; j >= 1; j >>= 1) REG_PASS(k, j);
        }
        selKeys[xa] = a; selKeys[xb] = c;
        __syncthreads();

        // ---- Phase 4b: permute boxes into sorted order (parallel) ----
        for (int i = tid; i < SEL_CAP; i += NT) {
            int sl = (int)(selKeys[i] & 0x3FF);
            sortedBoxes[i] = selBoxes[sl];
            sortedHalf[i]  = selHalf[sl];
        }
        __syncthreads();

        // ---- Phase 5: branchless dual-candidate greedy (warp 0) ----
        if (w == 0) {
            const float4 sent = make_float4(1e30f, 1e30f, -1e30f, -1e30f);
            float4 k0s = sent, k1s = sent, k2s = sent, k3s = sent;
            int nkept = 0;

            float4 b0 = sortedBoxes[0], b1 = sortedBoxes[1];
            float  h0 = sortedHalf[0],  h1 = sortedHalf[1];

            for (int cd = 0; cd < nsel && nkept < NMS_R; cd += 2) {
                float4 c0 = b0, c1 = b1;
                float  ha0 = h0, ha1 = h1;
                int p2 = (cd + 2) & (SEL_CAP - 1), p3 = (cd + 3) & (SEL_CAP - 1);
                b0 = sortedBoxes[p2]; h0 = sortedHalf[p2];
                b1 = sortedBoxes[p3]; h1 = sortedHalf[p3];

                bool s0 = iou_sup(k0s, c0, ha0) | iou_sup(k1s, c0, ha0)
                        | iou_sup(k2s, c0, ha0) | iou_sup(k3s, c0, ha0);
                bool s1 = iou_sup(k0s, c1, ha1) | iou_sup(k1s, c1, ha1)
                        | iou_sup(k2s, c1, ha1) | iou_sup(k3s, c1, ha1);

                unsigned bal0 = __ballot_sync(0xFFFFFFFFu, s0);
                unsigned bal1 = __ballot_sync(0xFFFFFFFFu, s1);

                bool keep0 = (bal0 == 0u);
                // c1 vs c0 (computed identically by every lane)
                float il = fmaxf(c0.x, c1.x), it = fmaxf(c0.y, c1.y);
                float ir = fminf(c0.z, c1.z), ib = fminf(c0.w, c1.w);
                float pin = fmaxf(0.0f, ir - il) * fmaxf(0.0f, ib - it);
                bool keep1 = (cd + 1 < nsel) && (bal1 == 0u) && !(keep0 && (pin >= ha1));

                int pos0 = nkept;
                int pos1 = nkept + (keep0 ? 1 : 0);

                bool m0 = keep0 && ((pos0 & 31) == lane);
                int  sl0 = pos0 >> 5;
                selset(k0s, c0, m0 && sl0 == 0);
                selset(k1s, c0, m0 && sl0 == 1);
                selset(k2s, c0, m0 && sl0 == 2);
                selset(k3s, c0, m0 && sl0 == 3);

                bool m1 = keep1 && ((pos1 & 31) == lane) && (pos1 < 128);
                int  sl1 = pos1 >> 5;
                selset(k0s, c1, m1 && sl1 == 0);
                selset(k1s, c1, m1 && sl1 == 1);
                selset(k2s, c1, m1 && sl1 == 2);
                selset(k3s, c1, m1 && sl1 == 3);

                if (keep0 && lane == 0) {
                    keptVals[pos0 * 3 + 0] = c0.y;
                    keptVals[pos0 * 3 + 1] = c0.z;
                    keptVals[pos0 * 3 + 2] = c0.w;
                }
                if (keep1 && lane == 1 && pos1 < NMS_R) {
                    keptVals[pos1 * 3 + 0] = c1.y;
                    keptVals[pos1 * 3 + 1] = c1.z;
                    keptVals[pos1 * 3 + 2] = c1.w;
                }
                nkept = pos1 + (keep1 ? 1 : 0);
            }
            if (lane == 0) sh_nkept = (nkept < NMS_R) ? nkept : NMS_R;
        }
        __syncthreads();
        if (tid == 0 && sh_nkept < NMS_R) fbFlag = 1;
        __syncthreads();
    }

    // ---- Fallback: full 2048 sort + greedy (exact, rarely taken) ----
    if (fbFlag) {
        #pragma unroll
        for (int p = 0; p < EPT; p++) {
            int e = tid + p * NT;
            fullKeys[e] = ((ull)(~float_to_ordered(sc[p])) << 32) | (unsigned)e;
        }
        __syncthreads();
        for (unsigned int k = 2; k <= NMS_N; k <<= 1) {
            for (unsigned int j = k >> 1; j > 0; j >>= 1) {
                #pragma unroll
                for (int p = 0; p < 4; p++) {
                    unsigned int i  = tid + p * NT;
                    unsigned int lo = ((i & ~(j - 1)) << 1) | (i & (j - 1));
                    unsigned int hi = lo | j;
                    ull u = fullKeys[lo], v = fullKeys[hi];
                    bool dir = ((lo & k) == 0);
                    if ((u > v) == dir) { fullKeys[lo] = v; fullKeys[hi] = u; }
                }
                __syncthreads();
            }
        }
        if (w == 0) {
            const float4 sent = make_float4(1e30f, 1e30f, -1e30f, -1e30f);
            float4 k0s = sent, k1s = sent, k2s = sent, k3s = sent;
            int nkept = 0;
            int idx_n = (int)(fullKeys[0] & 0x7FF);
            const float* pn = batch + (size_t)idx_n * 5;
            float l_n = __ldg(pn + 1), t_n = __ldg(pn + 2), r_n = __ldg(pn + 3), b_n = __ldg(pn + 4);
            for (int cd = 0; cd < NMS_N && nkept < NMS_R; ++cd) {
                float4 cb = make_float4(l_n, t_n, r_n, b_n);
                if (cd + 1 < NMS_N) {
                    idx_n = (int)(fullKeys[cd + 1] & 0x7FF);
                    const float* p2 = batch + (size_t)idx_n * 5;
                    l_n = __ldg(p2 + 1); t_n = __ldg(p2 + 2); r_n = __ldg(p2 + 3); b_n = __ldg(p2 + 4);
                }
                float hh = 0.5f * (cb.z - cb.x) * (cb.w - cb.y);
                bool sup = iou_sup(k0s, cb, hh) | iou_sup(k1s, cb, hh)
                         | iou_sup(k2s, cb, hh) | iou_sup(k3s, cb, hh);
                unsigned bal = __ballot_sync(0xFFFFFFFFu, sup);
                bool keep = (bal == 0u);
                bool m = keep && ((nkept & 31) == lane);
                int  sl = nkept >> 5;
                selset(k0s, cb, m && sl == 0);
                selset(k1s, cb, m && sl == 1);
                selset(k2s, cb, m && sl == 2);
                selset(k3s, cb, m && sl == 3);
                if (keep && lane == 0) {
                    keptVals[nkept * 3 + 0] = cb.y;
                    keptVals[nkept * 3 + 1] = cb.z;
                    keptVals[nkept * 3 + 2] = cb.w;
                }
                nkept += keep ? 1 : 0;
            }
            if (lane == 0) sh_nkept = nkept;
        }
        __syncthreads();
    }

    // ---- Output: [R,3], zero-padded ----
    int nk = sh_nkept;
    for (int o = tid; o < NMS_R * 3; o += NT) {
        int slot = o / 3;
        out[(size_t)b * NMS_R * 3 + o] = (slot < nk) ? keptVals[o] : 0.0f;
    }
}

extern "C" void kernel_launch(void* const* d_in, const int* in_sizes, int n_in,
                              void* d_out, int out_size) {
    const float* pred = (const float*)d_in[0];
    float* out = (float*)d_out;
    nms_kernel<<<32, NT>>>(pred, out);
}